// round 1
// baseline (speedup 1.0000x reference)
#include <cuda_runtime.h>

#define BSZ 8
#define SEQ 16
#define DIM 4096
#define NH 32
#define NKV 8
#define HD 128
#define CL 4096
#define NT (BSZ*SEQ)                 // 128 tokens
#define NQKV (DIM + 2*NKV*HD)        // 6144
#define CACHE_ELEMS (BSZ*CL*NKV*HD)  // 33554432
#define CK_OFF ((size_t)NT*DIM)      // 524288
#define CV_OFF (CK_OFF + CACHE_ELEMS)
#define RSQRT_HD 0.08838834764831845f

__device__ float g_qkv[(size_t)NT*NQKV];   // [128][6144]: q | k | v per token
__device__ float g_attn[(size_t)NT*DIM];   // [128][4096] attention output

// ---------------------------------------------------------------------------
// GEMM: C[m][n] = sum_k A[m][k] * W[n][k];  M=128 (BM=64 via blockIdx.y),
// K=4096, BN=64, BK=32. 256 threads, 4x4 microtile, register prefetch.
// ---------------------------------------------------------------------------
#define BK 32
__global__ __launch_bounds__(256) void gemm_tn(
    const float* __restrict__ A, const float* __restrict__ W,
    float* __restrict__ C, int ldc)
{
    __shared__ float Xs[BK][64];
    __shared__ float Ws[BK][64];
    const int m0 = blockIdx.y * 64;
    const int n0 = blockIdx.x * 64;
    const int t  = threadIdx.x;
    const int tm = t >> 4, tn = t & 15;

    const int lr = t >> 2;      // row within 64-tile
    const int lq = t & 3;       // k-quarter (8 floats)
    const float* Ap = A + (size_t)(m0 + lr) * DIM + lq * 8;
    const float* Wp = W + (size_t)(n0 + lr) * DIM + lq * 8;

    float acc[4][4] = {};

    float4 xa = *(const float4*)(Ap + 0);
    float4 xb = *(const float4*)(Ap + 4);
    float4 wa = *(const float4*)(Wp + 0);
    float4 wb = *(const float4*)(Wp + 4);

    for (int k0 = 0; k0 < DIM; k0 += BK) {
        __syncthreads();
        Xs[lq*8+0][lr]=xa.x; Xs[lq*8+1][lr]=xa.y; Xs[lq*8+2][lr]=xa.z; Xs[lq*8+3][lr]=xa.w;
        Xs[lq*8+4][lr]=xb.x; Xs[lq*8+5][lr]=xb.y; Xs[lq*8+6][lr]=xb.z; Xs[lq*8+7][lr]=xb.w;
        Ws[lq*8+0][lr]=wa.x; Ws[lq*8+1][lr]=wa.y; Ws[lq*8+2][lr]=wa.z; Ws[lq*8+3][lr]=wa.w;
        Ws[lq*8+4][lr]=wb.x; Ws[lq*8+5][lr]=wb.y; Ws[lq*8+6][lr]=wb.z; Ws[lq*8+7][lr]=wb.w;
        __syncthreads();

        int kn = (k0 + BK < DIM) ? (k0 + BK) : 0;   // safe prefetch
        xa = *(const float4*)(Ap + kn);
        xb = *(const float4*)(Ap + kn + 4);
        wa = *(const float4*)(Wp + kn);
        wb = *(const float4*)(Wp + kn + 4);

        #pragma unroll
        for (int k = 0; k < BK; k++) {
            float4 a = *(const float4*)&Xs[k][tm*4];
            float4 b = *(const float4*)&Ws[k][tn*4];
            acc[0][0] += a.x*b.x; acc[0][1] += a.x*b.y; acc[0][2] += a.x*b.z; acc[0][3] += a.x*b.w;
            acc[1][0] += a.y*b.x; acc[1][1] += a.y*b.y; acc[1][2] += a.y*b.z; acc[1][3] += a.y*b.w;
            acc[2][0] += a.z*b.x; acc[2][1] += a.z*b.y; acc[2][2] += a.z*b.z; acc[2][3] += a.z*b.w;
            acc[3][0] += a.w*b.x; acc[3][1] += a.w*b.y; acc[3][2] += a.w*b.z; acc[3][3] += a.w*b.w;
        }
    }

    #pragma unroll
    for (int i = 0; i < 4; i++)
        #pragma unroll
        for (int j = 0; j < 4; j++)
            C[(size_t)(m0 + tm*4 + i) * ldc + n0 + tn*4 + j] = acc[i][j];
}

// ---------------------------------------------------------------------------
// RoPE: in-place on q (cols 0..4095) and k (cols 4096..5119) of g_qkv.
// Pairs are adjacent elements; pair index within head = (col/2) % 64.
// ---------------------------------------------------------------------------
__global__ __launch_bounds__(256) void rope_kernel(
    float* __restrict__ qkv, const float* __restrict__ freqs)
{
    int idx = blockIdx.x * 256 + threadIdx.x;
    const int npairs = NT * 2560;       // (4096+1024)/2 per token
    if (idx >= npairs) return;
    int tok = idx / 2560;
    int p   = idx % 2560;
    int s   = tok & (SEQ - 1);
    int pd  = p & 63;
    float cs = freqs[s*128 + pd*2 + 0];
    float sn = freqs[s*128 + pd*2 + 1];
    float* base = qkv + (size_t)tok * NQKV + 2*p;
    float re = base[0], im = base[1];
    base[0] = re*cs - im*sn;
    base[1] = re*sn + im*cs;
}

// ---------------------------------------------------------------------------
// Cache shift + append: cout[b][t] = cin[b][t+16] for t<4080, else new k/v
// (already RoPE'd in g_qkv). float4 throughout.
// ---------------------------------------------------------------------------
__global__ __launch_bounds__(256) void cache_update(
    const float* __restrict__ cin, float* __restrict__ cout,
    const float* __restrict__ src /* g_qkv + col offset of k or v */)
{
    const int total = CACHE_ELEMS / 4;           // 8388608 float4
    int i = blockIdx.x * 256 + threadIdx.x;
    if (i >= total) return;
    const int ROW4 = NKV * HD / 4;               // 256 float4 per t-row
    int b    = i / (CL * ROW4);
    int r    = i % (CL * ROW4);
    int tpos = r / ROW4;
    int c    = r % ROW4;
    float4 v;
    if (tpos < CL - SEQ) {
        v = ((const float4*)cin)[(size_t)(b * CL + tpos + SEQ) * ROW4 + c];
    } else {
        int s   = tpos - (CL - SEQ);
        int tok = b * SEQ + s;
        v = *(const float4*)(src + (size_t)tok * NQKV + c * 4);
    }
    ((float4*)cout)[i] = v;
}

// ---------------------------------------------------------------------------
// Attention: one block per (b, h). 256 threads, 512-key chunks, online softmax.
// q pre-scaled by 1/sqrt(HD). mask added to scores.
// ---------------------------------------------------------------------------
#define CHUNK 512
__global__ __launch_bounds__(256) void attn_kernel(
    const float* __restrict__ qkv, const float* __restrict__ Kc,
    const float* __restrict__ Vc, const float* __restrict__ mask,
    float* __restrict__ attn_out)
{
    __shared__ float q_s[SEQ][HD];        // 8 KB
    __shared__ float s_s[SEQ][CHUNK];     // 32 KB
    __shared__ float m_s[SEQ], l_s[SEQ], sc_s[SEQ];

    const int t   = threadIdx.x;
    const int b   = blockIdx.x / NH;
    const int h   = blockIdx.x % NH;
    const int kvh = h >> 2;               // n_rep = 4

    for (int i = t; i < SEQ * HD; i += 256) {
        int s = i / HD, d = i % HD;
        q_s[s][d] = qkv[(size_t)(b*SEQ + s) * NQKV + h*HD + d] * RSQRT_HD;
    }
    if (t < SEQ) { m_s[t] = -1e30f; l_s[t] = 0.f; }
    __syncthreads();

    const int dp = t & 63;                // d = 2*dp, 2*dp+1
    const int qg = t >> 6;                // queries qg*4 .. qg*4+3
    float acc[4][2] = {};

    const float* Kb = Kc + (size_t)b * CL * (NKV*HD) + kvh * HD;
    const float* Vb = Vc + (size_t)b * CL * (NKV*HD) + kvh * HD;

    for (int c0 = 0; c0 < CL; c0 += CHUNK) {
        // ---- Phase 1: scores for keys c0+t and c0+t+256 ----
        {
            const float* kA = Kb + (size_t)(c0 + t) * (NKV*HD);
            const float* kB = kA + (size_t)256 * (NKV*HD);
            float dA[16] = {}, dB[16] = {};
            #pragma unroll 8
            for (int d0 = 0; d0 < HD; d0 += 4) {
                float4 a  = *(const float4*)(kA + d0);
                float4 bb = *(const float4*)(kB + d0);
                #pragma unroll
                for (int q = 0; q < 16; q++) {
                    float4 qv = *(const float4*)&q_s[q][d0];
                    dA[q] += a.x*qv.x + a.y*qv.y + a.z*qv.z + a.w*qv.w;
                    dB[q] += bb.x*qv.x + bb.y*qv.y + bb.z*qv.z + bb.w*qv.w;
                }
            }
            #pragma unroll
            for (int q = 0; q < 16; q++) {
                s_s[q][t]       = dA[q] + mask[q*CL + c0 + t];
                s_s[q][t + 256] = dB[q] + mask[q*CL + c0 + t + 256];
            }
        }
        __syncthreads();

        // ---- Phase 2: online softmax update (warp w -> rows 2w, 2w+1) ----
        {
            int w = t >> 5, lane = t & 31;
            for (int rr = 0; rr < 2; rr++) {
                int q = w*2 + rr;
                float mx = -1e30f;
                for (int j = lane; j < CHUNK; j += 32) mx = fmaxf(mx, s_s[q][j]);
                #pragma unroll
                for (int o = 16; o; o >>= 1) mx = fmaxf(mx, __shfl_xor_sync(0xffffffffu, mx, o));
                float mnew = fmaxf(m_s[q], mx);
                float sum = 0.f;
                for (int j = lane; j < CHUNK; j += 32) {
                    float p = __expf(s_s[q][j] - mnew);
                    s_s[q][j] = p;
                    sum += p;
                }
                #pragma unroll
                for (int o = 16; o; o >>= 1) sum += __shfl_xor_sync(0xffffffffu, sum, o);
                if (lane == 0) {
                    float sc = __expf(m_s[q] - mnew);
                    sc_s[q] = sc;
                    l_s[q]  = l_s[q] * sc + sum;
                    m_s[q]  = mnew;
                }
            }
        }
        __syncthreads();

        // ---- Phase 3: P @ V accumulation ----
        #pragma unroll
        for (int i = 0; i < 4; i++) {
            float sc = sc_s[qg*4 + i];
            acc[i][0] *= sc; acc[i][1] *= sc;
        }
        const float* vrow = Vb + (size_t)c0 * (NKV*HD) + 2*dp;
        for (int j0 = 0; j0 < CHUNK; j0 += 4) {
            float2 v0 = *(const float2*)(vrow + (size_t)(j0+0) * (NKV*HD));
            float2 v1 = *(const float2*)(vrow + (size_t)(j0+1) * (NKV*HD));
            float2 v2 = *(const float2*)(vrow + (size_t)(j0+2) * (NKV*HD));
            float2 v3 = *(const float2*)(vrow + (size_t)(j0+3) * (NKV*HD));
            #pragma unroll
            for (int i = 0; i < 4; i++) {
                float4 p = *(const float4*)&s_s[qg*4 + i][j0];
                acc[i][0] += p.x*v0.x + p.y*v1.x + p.z*v2.x + p.w*v3.x;
                acc[i][1] += p.x*v0.y + p.y*v1.y + p.z*v2.y + p.w*v3.y;
            }
        }
        __syncthreads();   // s_s reused next chunk
    }

    #pragma unroll
    for (int i = 0; i < 4; i++) {
        int q = qg*4 + i;
        float inv = 1.f / l_s[q];
        int tok = b*SEQ + q;
        attn_out[(size_t)tok * DIM + h*HD + 2*dp + 0] = acc[i][0] * inv;
        attn_out[(size_t)tok * DIM + h*HD + 2*dp + 1] = acc[i][1] * inv;
    }
}

// ---------------------------------------------------------------------------
extern "C" void kernel_launch(void* const* d_in, const int* in_sizes, int n_in,
                              void* d_out, int out_size)
{
    const float* x     = (const float*)d_in[0];
    const float* mask  = (const float*)d_in[1];
    const float* freqs = (const float*)d_in[2];
    const float* ck    = (const float*)d_in[3];
    const float* cv    = (const float*)d_in[4];
    const float* wq    = (const float*)d_in[5];
    const float* wk    = (const float*)d_in[6];
    const float* wv    = (const float*)d_in[7];
    const float* wo    = (const float*)d_in[8];
    float* out = (float*)d_out;

    float *qkv, *attn;
    cudaGetSymbolAddress((void**)&qkv, g_qkv);
    cudaGetSymbolAddress((void**)&attn, g_attn);

    // QKV projections
    gemm_tn<<<dim3(DIM/64, 2), 256>>>(x, wq, qkv, NQKV);
    gemm_tn<<<dim3((NKV*HD)/64, 2), 256>>>(x, wk, qkv + DIM, NQKV);
    gemm_tn<<<dim3((NKV*HD)/64, 2), 256>>>(x, wv, qkv + DIM + NKV*HD, NQKV);

    // RoPE on q and k
    rope_kernel<<<(NT*2560 + 255)/256, 256>>>(qkv, freqs);

    // Cache shift + append (writes cache_k / cache_v outputs)
    int cb = (CACHE_ELEMS/4 + 255) / 256;
    cache_update<<<cb, 256>>>(ck, out + CK_OFF, qkv + DIM);
    cache_update<<<cb, 256>>>(cv, out + CV_OFF, qkv + DIM + NKV*HD);

    // Attention over the updated caches
    attn_kernel<<<BSZ*NH, 256>>>(qkv, out + CK_OFF, out + CV_OFF, mask, attn);

    // Output projection
    gemm_tn<<<dim3(DIM/64, 2), 256>>>(attn, wo, out, DIM);
}